// round 12
// baseline (speedup 1.0000x reference)
#include <cuda_runtime.h>
#include <cstdint>

// ---------------------------------------------------------------------------
// MoE router: 3xTF32 mma.sync GEMM (16384x64x2048) + fused softmax/top-2.
// sm_80-compatible PTX only. R12 = R6 shape (TM=64, 4 warps, warp tile 32x32,
// grid 256, occ 2) + fragment-ready smem layouts: every LDS is
// [base_reg + constant] (no per-load address math, conflict-free), 3-stage
// cp.async pipeline, one barrier per tile.
// Precision (R6-proven, rel_err 7.8e-7): accS = exact hi*hi slab (32 K),
// folded rn into accT; cross terms in separate small-magnitude accL.
// ---------------------------------------------------------------------------

namespace {
constexpr int TOKENS = 16384;
constexpr int DK     = 2048;
constexpr int E      = 64;
constexpr int TM     = 64;         // tokens per CTA
constexpr int KC     = 32;         // K per pipeline stage (= slab)
constexpr int NTILES = DK / KC;    // 64
constexpr int NT     = 128;        // threads per CTA (4 warps)
constexpr int STAGES = 3;

constexpr size_t OFF_PROBS = (size_t)TOKENS * E;
constexpr size_t OFF_TKP   = OFF_PROBS + (size_t)TOKENS * E;
constexpr size_t OFF_TKI   = OFF_TKP + (size_t)TOKENS * 2;

// A stage: frag-ready [grp=4][ks=4][i=4][lane=32] f32 = 8192 B
// B stage: padded row-major [k=32][72] f32 (stride 288 B)   = 9216 B
constexpr int A_STAGE = 8192;
constexpr int B_POOL  = STAGES * A_STAGE;          // 24576
constexpr int B_STAGE = 9216;
constexpr int SMEM_SZ = B_POOL + STAGES * B_STAGE; // 52224
}

__device__ __forceinline__ uint32_t smem_u32(const void* p) {
    uint32_t a;
    asm("{ .reg .u64 t; cvta.to.shared.u64 t, %1; cvt.u32.u64 %0, t; }" : "=r"(a) : "l"(p));
    return a;
}
__device__ __forceinline__ void cp16(uint32_t s, const void* g) {
    asm volatile("cp.async.cg.shared.global [%0], [%1], 16;" :: "r"(s), "l"(g));
}
#define CP_COMMIT() asm volatile("cp.async.commit_group;" ::: "memory")
#define CP_WAIT1()  asm volatile("cp.async.wait_group 1;" ::: "memory")
#define CP_WAIT0()  asm volatile("cp.async.wait_group 0;" ::: "memory")

__device__ __forceinline__ uint32_t lds32(uint32_t addr) {
    uint32_t v;
    asm volatile("ld.shared.b32 %0, [%1];" : "=r"(v) : "r"(addr));
    return v;
}

#define MMA8(c, a, b)                                                          \
    asm volatile(                                                              \
        "mma.sync.aligned.m16n8k8.row.col.f32.tf32.tf32.f32 "                  \
        "{%0,%1,%2,%3}, {%4,%5,%6,%7}, {%8,%9}, {%0,%1,%2,%3};"                \
        : "+f"((c)[0]), "+f"((c)[1]), "+f"((c)[2]), "+f"((c)[3])               \
        : "r"((a)[0]), "r"((a)[1]), "r"((a)[2]), "r"((a)[3]),                  \
          "r"((b)[0]), "r"((b)[1]))

__global__ __launch_bounds__(NT, 2) void moe_router_mma(
    const float* __restrict__ x, const float* __restrict__ W, float* __restrict__ out)
{
    extern __shared__ __align__(16) char smem[];
    const uint32_t sbase = smem_u32(smem);

    const int tid  = threadIdx.x;
    const int wid  = tid >> 5;        // 0..3
    const int lane = tid & 31;
    const int wm   = wid >> 1;        // warp row: tokens [wm*32, +32)
    const int wn   = wid & 1;         // warp col: experts [wn*32, +32)
    const int g    = lane >> 2;
    const int tig  = lane & 3;
    const int tokBase = blockIdx.x * TM;

    float accT[2][4][4];   // hi-pass running total (chain of exact slabs)
    float accL[2][4][4];   // cross-pass accumulator, small magnitude
    #pragma unroll
    for (int mt = 0; mt < 2; mt++)
        #pragma unroll
        for (int nt = 0; nt < 4; nt++)
            #pragma unroll
            for (int i = 0; i < 4; i++) { accT[mt][nt][i] = 0.f; accL[mt][nt][i] = 0.f; }

    // ---- producers: cp.async into fragment-ready layouts ----
    // A chunk (row, kc): elements k = kc*4..kc*4+3 land lane-consecutive at
    //   dst = ((grp*4 + ks)*4 + i)*128 + (row&7)*16,
    //   grp=row>>4, ks=kc>>1, i=((row>>3)&1) + 2*(kc&1).
    // B chunk (k, nc): dst = k*288 + nc*16  (padded row-major).
    auto issue = [&](int t) {
        const int st = t % STAGES;
        const uint32_t Ab = sbase + st * A_STAGE;
        const uint32_t Bb = sbase + B_POOL + st * B_STAGE;
        const float* xt = x + (size_t)tokBase * DK + t * KC;
        #pragma unroll
        for (int j = 0; j < 4; j++) {
            int idx = tid + j * NT;                 // 0..511
            int row = idx >> 3, kc = idx & 7;
            uint32_t dst = ((((row >> 4) * 4 + (kc >> 1)) * 4
                             + ((row >> 3) & 1) + 2 * (kc & 1)) << 7)
                           + ((row & 7) << 4);
            cp16(Ab + dst, xt + (size_t)row * DK + kc * 4);
        }
        const float* wt = W + (size_t)t * KC * E;
        #pragma unroll
        for (int j = 0; j < 4; j++) {
            int idx = tid + j * NT;                 // 0..511
            int k = idx >> 4, nc = idx & 15;
            cp16(Bb + k * 288 + (nc << 4), wt + (size_t)k * E + nc * 4);
        }
    };

    issue(0); CP_COMMIT();
    issue(1); CP_COMMIT();

    for (int t = 0; t < NTILES; t++) {
        if (t + 2 < NTILES) { CP_WAIT1(); } else { CP_WAIT0(); }
        __syncthreads();   // stage t visible; oldest stage free to overwrite
        if (t + 2 < NTILES) { issue(t + 2); CP_COMMIT(); }

        const int st = t % STAGES;
        // per-warp bases: ALL fragment loads below are base + compile-time const
        const uint32_t base_a = sbase + st * A_STAGE + wm * 4096 + lane * 4;
        const uint32_t base_b = sbase + B_POOL + st * B_STAGE
                                + tig * 288 + wn * 128 + g * 4;

        // per-slab hi accumulator (exact tf32 products, 32 K-terms)
        float accS[2][4][4];
        #pragma unroll
        for (int mt = 0; mt < 2; mt++)
            #pragma unroll
            for (int nt = 0; nt < 4; nt++)
                #pragma unroll
                for (int i = 0; i < 4; i++) accS[mt][nt][i] = 0.f;

        #pragma unroll
        for (int ks = 0; ks < 4; ks++) {
            uint32_t ahi[2][4], alo[2][4];
            #pragma unroll
            for (int mt = 0; mt < 2; mt++) {
                #pragma unroll
                for (int i = 0; i < 4; i++) {
                    uint32_t raw = lds32(base_a + (((mt * 4 + ks) * 4 + i) << 7));
                    uint32_t hb = raw & 0xffffe000u;
                    float lo = __uint_as_float(raw) - __uint_as_float(hb);
                    ahi[mt][i] = hb;
                    alo[mt][i] = __float_as_uint(lo);
                }
            }
            uint32_t bhi[4][2], blo[4][2];
            #pragma unroll
            for (int nt = 0; nt < 4; nt++) {
                #pragma unroll
                for (int ib = 0; ib < 2; ib++) {
                    uint32_t raw = lds32(base_b + ks * 2304 + ib * 1152 + nt * 32);
                    uint32_t hb = raw & 0xffffe000u;
                    float lo = __uint_as_float(raw) - __uint_as_float(hb);
                    bhi[nt][ib] = hb;
                    blo[nt][ib] = __float_as_uint(lo);
                }
            }
            #pragma unroll
            for (int mt = 0; mt < 2; mt++) {
                #pragma unroll
                for (int nt = 0; nt < 4; nt++) {
                    MMA8(accS[mt][nt], ahi[mt], bhi[nt]);   // exact products
                    MMA8(accL[mt][nt], ahi[mt], blo[nt]);   // tiny cross terms
                    MMA8(accL[mt][nt], alo[mt], bhi[nt]);
                }
            }
        }

        // fold slab into running total (one rn-add per accumulator element)
        #pragma unroll
        for (int mt = 0; mt < 2; mt++)
            #pragma unroll
            for (int nt = 0; nt < 4; nt++)
                #pragma unroll
                for (int i = 0; i < 4; i++)
                    accT[mt][nt][i] = __fadd_rn(accT[mt][nt][i], accS[mt][nt][i]);
    }
    __syncthreads();

    // ---- epilogue: logits = T + L -> smem [64][66] ----
    float* L = (float*)smem;
    #pragma unroll
    for (int mt = 0; mt < 2; mt++) {
        #pragma unroll
        for (int nt = 0; nt < 4; nt++) {
            int row0 = wm * 32 + mt * 16 + g;
            int col  = wn * 32 + nt * 8 + tig * 2;
            float v0 = __fadd_rn(accT[mt][nt][0], accL[mt][nt][0]);
            float v1 = __fadd_rn(accT[mt][nt][1], accL[mt][nt][1]);
            float v2 = __fadd_rn(accT[mt][nt][2], accL[mt][nt][2]);
            float v3 = __fadd_rn(accT[mt][nt][3], accL[mt][nt][3]);
            *(float2*)&L[row0 * 66 + col]       = make_float2(v0, v1);
            *(float2*)&L[(row0 + 8) * 66 + col] = make_float2(v2, v3);
        }
    }
    __syncthreads();

    if (tid < TM) {
        const int token = tokBase + tid;
        float* lrow = &L[tid * 66];

        float l[64];
        #pragma unroll
        for (int e = 0; e < 64; e++) l[e] = lrow[e];

        // top-2; strict '>' keeps lower index on ties (matches lax.top_k)
        float m1 = -1e30f, m2 = -1e30f;
        int   i1 = 0,      i2 = 0;
        #pragma unroll
        for (int e = 0; e < 64; e++) {
            float v = l[e];
            if (v > m1)      { m2 = m1; i2 = i1; m1 = v; i1 = e; }
            else if (v > m2) { m2 = v;  i2 = e; }
        }

        float sum = 0.f;
        #pragma unroll
        for (int e = 0; e < 64; e++) { l[e] = expf(l[e] - m1); sum += l[e]; }
        const float inv = 1.0f / sum;

        float4* prow = (float4*)&out[OFF_PROBS + (size_t)token * 64];
        float4* drow = (float4*)&out[(size_t)token * 64];
        #pragma unroll
        for (int gq = 0; gq < 16; gq++) {
            float4 pv;
            pv.x = l[gq*4+0] * inv; pv.y = l[gq*4+1] * inv;
            pv.z = l[gq*4+2] * inv; pv.w = l[gq*4+3] * inv;
            prow[gq] = pv;
            float d0 = 0.f, d1 = 0.f, d2 = 0.f, d3 = 0.f;
            if ((i1 >> 2) == gq) { int r = i1 & 3; if (r==0) d0=1.f; else if (r==1) d1=1.f; else if (r==2) d2=1.f; else d3=1.f; }
            if ((i2 >> 2) == gq) { int r = i2 & 3; if (r==0) d0+=1.f; else if (r==1) d1+=1.f; else if (r==2) d2+=1.f; else d3+=1.f; }
            drow[gq] = make_float4(d0, d1, d2, d3);
        }
        out[OFF_TKP + (size_t)token * 2 + 0] = l[i1] * inv;
        out[OFF_TKP + (size_t)token * 2 + 1] = l[i2] * inv;
        out[OFF_TKI + (size_t)token * 2 + 0] = (float)i1;
        out[OFF_TKI + (size_t)token * 2 + 1] = (float)i2;
    }
}

extern "C" void kernel_launch(void* const* d_in, const int* in_sizes, int n_in,
                              void* d_out, int out_size) {
    const float* x = (const float*)d_in[0];
    const float* W = (const float*)d_in[1];
    float* out = (float*)d_out;
    cudaFuncSetAttribute(moe_router_mma, cudaFuncAttributeMaxDynamicSharedMemorySize, SMEM_SZ);
    moe_router_mma<<<TOKENS / TM, NT, SMEM_SZ>>>(x, W, out);
}

// round 14
// speedup vs baseline: 1.4308x; 1.4308x over previous
#include <cuda_runtime.h>
#include <cstdint>

// ---------------------------------------------------------------------------
// MoE router: 3xTF32 mma.sync GEMM (16384x64x2048) + fused softmax/top-2.
// sm_80-compatible PTX only. R13 = R6 layout/shape (TM=64, 4 warps, 32x32
// warp tile, XOR-swizzled smem conflict-free on BOTH producer and consumer)
// + KC=64 tiles (half the barriers/loop overhead), 3-stage cp.async,
// + direct C-chained accT for hi*hi (no slab accumulator, no folds).
// Precision: hi = fp32 masked to tf32 bits (exact products in fp32);
// cross terms (Ah*Bl + Al*Bh) in separate small-magnitude accL.
// ---------------------------------------------------------------------------

namespace {
constexpr int TOKENS = 16384;
constexpr int DK     = 2048;
constexpr int E      = 64;
constexpr int TM     = 64;         // tokens per CTA
constexpr int KC     = 64;         // K per pipeline stage
constexpr int NTILES = DK / KC;    // 32
constexpr int NT     = 128;        // threads per CTA (4 warps)
constexpr int STAGES = 3;

constexpr size_t OFF_PROBS = (size_t)TOKENS * E;
constexpr size_t OFF_TKP   = OFF_PROBS + (size_t)TOKENS * E;
constexpr size_t OFF_TKI   = OFF_TKP + (size_t)TOKENS * 2;

constexpr int A_STAGE = 16384;                     // 64x64 f32
constexpr int B_POOL  = STAGES * A_STAGE;          // 49152
constexpr int B_STAGE = 16384;                     // 64x64 f32
constexpr int SMEM_SZ = B_POOL + STAGES * B_STAGE; // 98304 (96KB, occ 2 ok)
}

__device__ __forceinline__ uint32_t smem_u32(const void* p) {
    uint32_t a;
    asm("{ .reg .u64 t; cvta.to.shared.u64 t, %1; cvt.u32.u64 %0, t; }" : "=r"(a) : "l"(p));
    return a;
}
__device__ __forceinline__ void cp16(uint32_t s, const void* g) {
    asm volatile("cp.async.cg.shared.global [%0], [%1], 16;" :: "r"(s), "l"(g));
}
#define CP_COMMIT() asm volatile("cp.async.commit_group;" ::: "memory")
#define CP_WAIT1()  asm volatile("cp.async.wait_group 1;" ::: "memory")
#define CP_WAIT0()  asm volatile("cp.async.wait_group 0;" ::: "memory")

__device__ __forceinline__ uint32_t lds32(uint32_t addr) {
    uint32_t v;
    asm volatile("ld.shared.b32 %0, [%1];" : "=r"(v) : "r"(addr));
    return v;
}

#define MMA8(c, a, b)                                                          \
    asm volatile(                                                              \
        "mma.sync.aligned.m16n8k8.row.col.f32.tf32.tf32.f32 "                  \
        "{%0,%1,%2,%3}, {%4,%5,%6,%7}, {%8,%9}, {%0,%1,%2,%3};"                \
        : "+f"((c)[0]), "+f"((c)[1]), "+f"((c)[2]), "+f"((c)[3])               \
        : "r"((a)[0]), "r"((a)[1]), "r"((a)[2]), "r"((a)[3]),                  \
          "r"((b)[0]), "r"((b)[1]))

__global__ __launch_bounds__(NT, 2) void moe_router_mma(
    const float* __restrict__ x, const float* __restrict__ W, float* __restrict__ out)
{
    extern __shared__ __align__(16) char smem[];
    const uint32_t sbase = smem_u32(smem);

    const int tid  = threadIdx.x;
    const int wid  = tid >> 5;        // 0..3
    const int lane = tid & 31;
    const int wm   = wid >> 1;        // warp row: tokens [wm*32, +32)
    const int wn   = wid & 1;         // warp col: experts [wn*32, +32)
    const int g    = lane >> 2;
    const int tig  = lane & 3;
    const int tokBase = blockIdx.x * TM;

    float accT[2][4][4];   // hi*hi, C-chained through MMA (error ~5.5e-7)
    float accL[2][4][4];   // cross terms, small magnitude
    #pragma unroll
    for (int mt = 0; mt < 2; mt++)
        #pragma unroll
        for (int nt = 0; nt < 4; nt++)
            #pragma unroll
            for (int i = 0; i < 4; i++) { accT[mt][nt][i] = 0.f; accL[mt][nt][i] = 0.f; }

    // A[row 0..63][64 k]: chunk ch 0..15 of 4 floats, phys = ch ^ (row&7)
    // B[k 0..63][64 e]:   chunk ch 0..15 of 4 floats, phys = ch ^ (2*(k&3))
    auto issue = [&](int t) {
        const int st = t % STAGES;
        const uint32_t Ab = sbase + st * A_STAGE;
        const uint32_t Bb = sbase + B_POOL + st * B_STAGE;
        const float* xt = x + (size_t)tokBase * DK + t * KC;
        #pragma unroll
        for (int j = 0; j < 8; j++) {
            int idx = tid + j * NT;                 // 0..1023
            int row = idx >> 4, ch = idx & 15;
            cp16(Ab + row * 256 + ((ch ^ (row & 7)) << 4),
                 xt + (size_t)row * DK + ch * 4);
        }
        const float* wt = W + (size_t)t * KC * E;
        #pragma unroll
        for (int j = 0; j < 8; j++) {
            int idx = tid + j * NT;                 // 0..1023
            int k = idx >> 4, ch = idx & 15;
            cp16(Bb + k * 256 + ((ch ^ (2 * (k & 3))) << 4),
                 wt + (size_t)k * E + ch * 4);
        }
    };

    issue(0); CP_COMMIT();
    issue(1); CP_COMMIT();

    for (int t = 0; t < NTILES; t++) {
        if (t + 2 < NTILES) { CP_WAIT1(); } else { CP_WAIT0(); }
        __syncthreads();   // stage t visible; oldest stage free to overwrite
        if (t + 2 < NTILES) { issue(t + 2); CP_COMMIT(); }

        const int st = t % STAGES;
        const uint32_t Ab = sbase + st * A_STAGE;
        const uint32_t Bb = sbase + B_POOL + st * B_STAGE;

        #pragma unroll
        for (int ks = 0; ks < 8; ks++) {
            uint32_t ahi[2][4], alo[2][4];
            #pragma unroll
            for (int mt = 0; mt < 2; mt++) {
                #pragma unroll
                for (int i = 0; i < 4; i++) {
                    int row = wm * 32 + mt * 16 + g + (i & 1) * 8;
                    int ch  = (i >> 1) + 2 * ks;
                    uint32_t addr = Ab + row * 256 + ((ch ^ (row & 7)) << 4) + tig * 4;
                    uint32_t raw = lds32(addr);
                    uint32_t hb = raw & 0xffffe000u;
                    float lo = __uint_as_float(raw) - __uint_as_float(hb);
                    ahi[mt][i] = hb;
                    alo[mt][i] = __float_as_uint(lo);
                }
            }
            uint32_t bhi[4][2], blo[4][2];
            #pragma unroll
            for (int nt = 0; nt < 4; nt++) {
                #pragma unroll
                for (int ib = 0; ib < 2; ib++) {
                    int k = ks * 8 + ib * 4 + tig;
                    int n = wn * 32 + nt * 8 + g;
                    int ch = n >> 2;
                    uint32_t addr = Bb + k * 256 + ((ch ^ (2 * tig)) << 4) + (n & 3) * 4;
                    uint32_t raw = lds32(addr);
                    uint32_t hb = raw & 0xffffe000u;
                    float lo = __uint_as_float(raw) - __uint_as_float(hb);
                    bhi[nt][ib] = hb;
                    blo[nt][ib] = __float_as_uint(lo);
                }
            }
            // pass-grouped: accT group, then the two accL groups
            #pragma unroll
            for (int mt = 0; mt < 2; mt++)
                #pragma unroll
                for (int nt = 0; nt < 4; nt++)
                    MMA8(accT[mt][nt], ahi[mt], bhi[nt]);   // exact products, C-chain
            #pragma unroll
            for (int mt = 0; mt < 2; mt++)
                #pragma unroll
                for (int nt = 0; nt < 4; nt++)
                    MMA8(accL[mt][nt], ahi[mt], blo[nt]);   // cross term 1
            #pragma unroll
            for (int mt = 0; mt < 2; mt++)
                #pragma unroll
                for (int nt = 0; nt < 4; nt++)
                    MMA8(accL[mt][nt], alo[mt], bhi[nt]);   // cross term 2
        }
    }
    __syncthreads();

    // ---- epilogue: logits = T + L -> smem [64][66] ----
    float* L = (float*)smem;
    #pragma unroll
    for (int mt = 0; mt < 2; mt++) {
        #pragma unroll
        for (int nt = 0; nt < 4; nt++) {
            int row0 = wm * 32 + mt * 16 + g;
            int col  = wn * 32 + nt * 8 + tig * 2;
            float v0 = __fadd_rn(accT[mt][nt][0], accL[mt][nt][0]);
            float v1 = __fadd_rn(accT[mt][nt][1], accL[mt][nt][1]);
            float v2 = __fadd_rn(accT[mt][nt][2], accL[mt][nt][2]);
            float v3 = __fadd_rn(accT[mt][nt][3], accL[mt][nt][3]);
            *(float2*)&L[row0 * 66 + col]       = make_float2(v0, v1);
            *(float2*)&L[(row0 + 8) * 66 + col] = make_float2(v2, v3);
        }
    }
    __syncthreads();

    if (tid < TM) {
        const int token = tokBase + tid;
        float* lrow = &L[tid * 66];

        float l[64];
        #pragma unroll
        for (int e = 0; e < 64; e++) l[e] = lrow[e];

        // top-2; strict '>' keeps lower index on ties (matches lax.top_k)
        float m1 = -1e30f, m2 = -1e30f;
        int   i1 = 0,      i2 = 0;
        #pragma unroll
        for (int e = 0; e < 64; e++) {
            float v = l[e];
            if (v > m1)      { m2 = m1; i2 = i1; m1 = v; i1 = e; }
            else if (v > m2) { m2 = v;  i2 = e; }
        }

        float sum = 0.f;
        #pragma unroll
        for (int e = 0; e < 64; e++) { l[e] = expf(l[e] - m1); sum += l[e]; }
        const float inv = 1.0f / sum;

        float4* prow = (float4*)&out[OFF_PROBS + (size_t)token * 64];
        float4* drow = (float4*)&out[(size_t)token * 64];
        #pragma unroll
        for (int gq = 0; gq < 16; gq++) {
            float4 pv;
            pv.x = l[gq*4+0] * inv; pv.y = l[gq*4+1] * inv;
            pv.z = l[gq*4+2] * inv; pv.w = l[gq*4+3] * inv;
            prow[gq] = pv;
            float d0 = 0.f, d1 = 0.f, d2 = 0.f, d3 = 0.f;
            if ((i1 >> 2) == gq) { int r = i1 & 3; if (r==0) d0=1.f; else if (r==1) d1=1.f; else if (r==2) d2=1.f; else d3=1.f; }
            if ((i2 >> 2) == gq) { int r = i2 & 3; if (r==0) d0+=1.f; else if (r==1) d1+=1.f; else if (r==2) d2+=1.f; else d3+=1.f; }
            drow[gq] = make_float4(d0, d1, d2, d3);
        }
        out[OFF_TKP + (size_t)token * 2 + 0] = l[i1] * inv;
        out[OFF_TKP + (size_t)token * 2 + 1] = l[i2] * inv;
        out[OFF_TKI + (size_t)token * 2 + 0] = (float)i1;
        out[OFF_TKI + (size_t)token * 2 + 1] = (float)i2;
    }
}

extern "C" void kernel_launch(void* const* d_in, const int* in_sizes, int n_in,
                              void* d_out, int out_size) {
    const float* x = (const float*)d_in[0];
    const float* W = (const float*)d_in[1];
    float* out = (float*)d_out;
    cudaFuncSetAttribute(moe_router_mma, cudaFuncAttributeMaxDynamicSharedMemorySize, SMEM_SZ);
    moe_router_mma<<<TOKENS / TM, NT, SMEM_SZ>>>(x, W, out);
}